// round 9
// baseline (speedup 1.0000x reference)
#include <cuda_runtime.h>
#include <cuda_fp16.h>
#include <math.h>
#include <stdint.h>

#define VSZ 8192

__device__ __align__(16) float g_enc[512 * 512];
__device__ __align__(16) float g_dec[128 * 512];
__device__ __align__(16) __half g_wvt[8192 * 512];   // [v][d] fp16 intermediate
__device__ __align__(16) int8_t g_wq[8192 * 512];    // [v][d] s8
__device__ __align__(16) float g_sb[8192];           // per-v scale

__device__ __forceinline__ uint32_t smem_u32(const void* p) {
    uint32_t a;
    asm("{ .reg .u64 t; cvta.to.shared.u64 t, %1; cvt.u32.u64 %0, t; }" : "=r"(a) : "l"(p));
    return a;
}
__device__ __forceinline__ void cpa16(uint32_t dst, const void* src) {
    asm volatile("cp.async.cg.shared.global [%0], [%1], 16;" :: "r"(dst), "l"(src));
}
#define CPA_COMMIT() asm volatile("cp.async.commit_group;" ::: "memory")
#define CPA_WAIT1()  asm volatile("cp.async.wait_group 1;" ::: "memory")
#define CPA_WAIT0()  asm volatile("cp.async.wait_group 0;" ::: "memory")
__device__ __forceinline__ void ldsm4(uint32_t* r, uint32_t a) {
    asm volatile("ldmatrix.sync.aligned.m8n8.x4.shared.b16 {%0,%1,%2,%3}, [%4];"
        : "=r"(r[0]), "=r"(r[1]), "=r"(r[2]), "=r"(r[3]) : "r"(a));
}
__device__ __forceinline__ void mma_i8(int* c, const uint32_t* a, const uint32_t* b) {
    asm("mma.sync.aligned.m16n8k32.row.col.s32.u8.s8.s32 "
        "{%0,%1,%2,%3}, {%4,%5,%6,%7}, {%8,%9}, {%0,%1,%2,%3};\n"
        : "+r"(c[0]), "+r"(c[1]), "+r"(c[2]), "+r"(c[3])
        : "r"(a[0]), "r"(a[1]), "r"(a[2]), "r"(a[3]), "r"(b[0]), "r"(b[1]));
}

// ---------------- prep ----------------
__global__ void k_encdec(const float* __restrict__ v, const float* __restrict__ t,
                         const float* __restrict__ W1, const float* __restrict__ b1,
                         const float* __restrict__ W2, const float* __restrict__ b2) {
    __shared__ float xr[4][512];
    int bid = blockIdx.x, tid = threadIdx.x;
    int rg = bid >> 2, cq = bid & 3;
    const float *in, *W, *bs; float* out;
    if (rg < 128) { in = v + (size_t)rg * 2048; W = W1; bs = b1; out = g_enc + (size_t)rg * 2048; }
    else { in = t + (size_t)(rg - 128) * 2048; W = W2; bs = b2; out = g_dec + (size_t)(rg - 128) * 2048; }
    #pragma unroll
    for (int i = 0; i < 8; ++i) ((float*)xr)[i * 256 + tid] = in[i * 256 + tid];
    __syncthreads();
    int c = cq * 128 + (tid & 127);
    int rp = tid >> 7;
    float bb = bs[c];
    float a0 = bb, a1 = bb;
    #pragma unroll 4
    for (int d = 0; d < 512; ++d) {
        float w = W[d * 512 + c];
        a0 = fmaf(xr[rp][d], w, a0);
        a1 = fmaf(xr[rp + 2][d], w, a1);
    }
    out[(size_t)rp * 512 + c] = a0;
    out[(size_t)(rp + 2) * 512 + c] = a1;
}

__global__ void k_cvt(const float* __restrict__ Wv) {
    __shared__ float tile[32][33];
    int bvi = blockIdx.x & 255, bd = blockIdx.x >> 8;
    int v0 = bvi * 32, d0 = bd * 32;
    int c = threadIdx.x & 31, r8 = threadIdx.x >> 5;
    #pragma unroll
    for (int i = 0; i < 4; ++i)
        tile[i * 8 + r8][c] = Wv[(size_t)(d0 + i * 8 + r8) * VSZ + v0 + c];
    __syncthreads();
    #pragma unroll
    for (int i = 0; i < 4; ++i)
        g_wvt[(size_t)(v0 + i * 8 + r8) * 512 + d0 + c] = __float2half(tile[c][i * 8 + r8]);
}

__global__ void k_cvt2() {
    int w = threadIdx.x >> 5, lane = threadIdx.x & 31;
    int vr = blockIdx.x * 8 + w;
    const uint4* row = (const uint4*)(g_wvt + (size_t)vr * 512);
    uint4 u0 = row[lane], u1 = row[lane + 32];
    float f[16];
    #pragma unroll
    for (int j = 0; j < 4; ++j) {
        float2 p = __half22float2(*(__half2*)&((uint32_t*)&u0)[j]);
        f[j * 2] = p.x; f[j * 2 + 1] = p.y;
        float2 q = __half22float2(*(__half2*)&((uint32_t*)&u1)[j]);
        f[8 + j * 2] = q.x; f[8 + j * 2 + 1] = q.y;
    }
    float m = 0.f;
    #pragma unroll
    for (int j = 0; j < 16; ++j) m = fmaxf(m, fabsf(f[j]));
    #pragma unroll
    for (int o = 16; o > 0; o >>= 1) m = fmaxf(m, __shfl_xor_sync(~0u, m, o));
    float rcp = (m > 0.f) ? 127.f / m : 0.f;
    if (lane == 0) g_sb[vr] = (m > 0.f) ? m * (1.f / 127.f) : 1.f;
    uint32_t* dst = (uint32_t*)(g_wq + (size_t)vr * 512);
    #pragma unroll
    for (int h = 0; h < 2; ++h) {
        uint32_t q0 = 0, q1 = 0;
        #pragma unroll
        for (int j = 0; j < 4; ++j) {
            int a = __float2int_rn(f[h * 8 + j] * rcp);
            int b = __float2int_rn(f[h * 8 + 4 + j] * rcp);
            q0 |= (uint32_t)(a & 255) << (j * 8);
            q1 |= (uint32_t)(b & 255) << (j * 8);
        }
        dst[h * 64 + lane * 2] = q0;
        dst[h * 64 + lane * 2 + 1] = q1;
    }
}

// ---- main int8 GEMM + fused log-softmax ----
// warp tile 64x32 (acc = 64 regs, no spills). N chunk 128, 64 chunks x 8 kb.
#define SA_STRB 528
#define SB_STRB 80
#define A_BYTES (128 * SA_STRB)
#define B_BYTES (128 * SB_STRB)
#define DYN_SMEM (A_BYTES + 2 * B_BYTES)

__global__ void __launch_bounds__(256, 1)
k_gemm2(const float* __restrict__ bv, float* __restrict__ out) {
    extern __shared__ char sm[];
    __shared__ float pmax[4][128], psum[4][128];
    __shared__ float rmax[128], rsum[128], slse[128];
    __shared__ float s_amax[128], s_sa[128], s_rcp[128];

    const uint32_t sA = smem_u32(sm);
    const uint32_t sB0 = sA + A_BYTES;
    int tid = threadIdx.x, lane = tid & 31, w = tid >> 5;
    int wm = w >> 2, wn = w & 3;
    int q = lane >> 2, l4 = lane & 3;
    int r0 = blockIdx.x * 128;

    if (tid < 128) { rmax[tid] = -1e30f; rsum[tid] = 0.f; s_amax[tid] = 0.f; }
    __syncthreads();

    // A phase 1: per-row max of relu(enc+dec)
    #pragma unroll 1
    for (int t2 = 0; t2 < 2; ++t2) {
        int task = t2 * 256 + tid;
        int r = task >> 2, kq = task & 3;
        int grow = r0 + r;
        const float4* ep = (const float4*)(g_enc + (size_t)(grow >> 6) * 512 + kq * 128);
        const float4* dp = (const float4*)(g_dec + (size_t)(((grow >> 14) << 6) | (grow & 63)) * 512 + kq * 128);
        float m = 0.f;
        #pragma unroll 8
        for (int i = 0; i < 32; ++i) {
            float4 e = ep[i], d = dp[i];
            m = fmaxf(m, fmaxf(fmaxf(e.x + d.x, e.y + d.y), fmaxf(e.z + d.z, e.w + d.w)));
        }
        atomicMax((int*)&s_amax[r], __float_as_int(fmaxf(m, 0.f)));
    }
    __syncthreads();
    if (tid < 128) {
        float m = s_amax[tid];
        s_sa[tid] = (m > 0.f) ? m * (1.f / 255.f) : 1.f;
        s_rcp[tid] = (m > 0.f) ? 255.f / m : 0.f;
    }
    __syncthreads();
    // A phase 2: quantize to u8 in smem
    #pragma unroll 1
    for (int t2 = 0; t2 < 2; ++t2) {
        int task = t2 * 256 + tid;
        int r = task >> 2, kq = task & 3;
        int grow = r0 + r;
        const float4* ep = (const float4*)(g_enc + (size_t)(grow >> 6) * 512 + kq * 128);
        const float4* dp = (const float4*)(g_dec + (size_t)(((grow >> 14) << 6) | (grow & 63)) * 512 + kq * 128);
        float rcp = s_rcp[r];
        #pragma unroll
        for (int g = 0; g < 8; ++g) {
            uint32_t buf[4];
            #pragma unroll
            for (int j = 0; j < 4; ++j) {
                float4 e = ep[g * 4 + j], d = dp[g * 4 + j];
                uint32_t q0 = __float2uint_rn(fmaxf(e.x + d.x, 0.f) * rcp);
                uint32_t q1 = __float2uint_rn(fmaxf(e.y + d.y, 0.f) * rcp);
                uint32_t q2 = __float2uint_rn(fmaxf(e.z + d.z, 0.f) * rcp);
                uint32_t q3 = __float2uint_rn(fmaxf(e.w + d.w, 0.f) * rcp);
                buf[j] = q0 | (q1 << 8) | (q2 << 16) | (q3 << 24);
            }
            *(uint4*)(sm + r * SA_STRB + kq * 128 + g * 16) = *(uint4*)buf;
        }
    }

    const uint32_t aBase = sA + (wm * 64 + (lane & 15)) * SA_STRB + (lane >> 4) * 16;
    const int bN = (lane & 7) + ((lane >> 4) << 3);
    const uint32_t bKh = ((lane >> 3) & 1) * 16;
    const uint32_t bBase = sB0 + (wn * 32 + bN) * SB_STRB + bKh;

    int acc[4][4][4];   // 64 regs

    // stage slab 0: 128 n x 64 B, 2 x 16B per thread
    #pragma unroll
    for (int i = 0; i < 2; ++i) {
        int flat = i * 256 + tid;
        int n = flat >> 2, c = flat & 3;
        cpa16(sB0 + n * SB_STRB + c * 16, g_wq + (size_t)n * 512 + c * 16);
    }
    CPA_COMMIT();

    #pragma unroll 1
    for (int s = 0; s < 512; ++s) {
        int vc = s >> 3, kb = s & 7, buf = s & 1;
        __syncthreads();
        if (s + 1 < 512) {
            int vn = (s + 1) >> 3, kn = (s + 1) & 7;
            uint32_t dst = sB0 + ((s + 1) & 1) * B_BYTES;
            const int8_t* src = g_wq + (size_t)vn * 128 * 512 + kn * 64;
            #pragma unroll
            for (int i = 0; i < 2; ++i) {
                int flat = i * 256 + tid;
                int n = flat >> 2, c = flat & 3;
                cpa16(dst + n * SB_STRB + c * 16, src + (size_t)n * 512 + c * 16);
            }
            CPA_COMMIT();
            CPA_WAIT1();
        } else {
            CPA_WAIT0();
        }
        __syncthreads();

        if (kb == 0) {
            #pragma unroll
            for (int am = 0; am < 4; ++am)
                #pragma unroll
                for (int an = 0; an < 4; ++an)
                    #pragma unroll
                    for (int j = 0; j < 4; ++j) acc[am][an][j] = 0;
        }

        uint32_t bB = bBase + buf * B_BYTES;
        uint32_t aK = aBase + kb * 64;
        #pragma unroll
        for (int ks = 0; ks < 2; ++ks) {
            uint32_t afr[4][4], bfr[2][4];
            #pragma unroll
            for (int am = 0; am < 4; ++am) ldsm4(afr[am], aK + am * 16 * SA_STRB + ks * 32);
            #pragma unroll
            for (int t = 0; t < 2; ++t) ldsm4(bfr[t], bB + t * 16 * SB_STRB + ks * 32);
            #pragma unroll
            for (int am = 0; am < 4; ++am)
                #pragma unroll
                for (int t = 0; t < 2; ++t) {
                    mma_i8(acc[am][2 * t],     afr[am], &bfr[t][0]);
                    mma_i8(acc[am][2 * t + 1], afr[am], &bfr[t][2]);
                }
        }

        if (kb == 7) {
            int v0 = vc * 128;
            #pragma unroll
            for (int am = 0; am < 4; ++am) {
                int rowl = wm * 64 + am * 16 + q;
                float sa0 = s_sa[rowl], sa1 = s_sa[rowl + 8];
                size_t gr0 = (size_t)(r0 + rowl) << 13;
                size_t gr1 = gr0 + (8u << 13);
                float mx0 = -1e30f, mx1 = -1e30f;
                #pragma unroll
                for (int an = 0; an < 4; ++an) {
                    int cc = v0 + wn * 32 + an * 8 + l4 * 2;
                    float2 sb2 = __ldg((const float2*)&g_sb[cc]);
                    float2 bv2 = __ldg((const float2*)&bv[cc]);
                    int* a4 = acc[am][an];
                    float z0 = (float)a4[0] * (sa0 * sb2.x) + bv2.x;
                    float z1 = (float)a4[1] * (sa0 * sb2.y) + bv2.y;
                    float z2 = (float)a4[2] * (sa1 * sb2.x) + bv2.x;
                    float z3 = (float)a4[3] * (sa1 * sb2.y) + bv2.y;
                    *(float2*)&out[gr0 + cc] = make_float2(z0, z1);
                    *(float2*)&out[gr1 + cc] = make_float2(z2, z3);
                    mx0 = fmaxf(mx0, fmaxf(z0, z1));
                    mx1 = fmaxf(mx1, fmaxf(z2, z3));
                    a4[0] = __float_as_int(z0); a4[1] = __float_as_int(z1);
                    a4[2] = __float_as_int(z2); a4[3] = __float_as_int(z3);
                }
                mx0 = fmaxf(mx0, __shfl_xor_sync(~0u, mx0, 1));
                mx0 = fmaxf(mx0, __shfl_xor_sync(~0u, mx0, 2));
                mx1 = fmaxf(mx1, __shfl_xor_sync(~0u, mx1, 1));
                mx1 = fmaxf(mx1, __shfl_xor_sync(~0u, mx1, 2));
                float s0 = 0.f, s1 = 0.f;
                #pragma unroll
                for (int an = 0; an < 4; ++an) {
                    int* a4 = acc[am][an];
                    s0 += __expf(__int_as_float(a4[0]) - mx0) + __expf(__int_as_float(a4[1]) - mx0);
                    s1 += __expf(__int_as_float(a4[2]) - mx1) + __expf(__int_as_float(a4[3]) - mx1);
                }
                s0 += __shfl_xor_sync(~0u, s0, 1);
                s0 += __shfl_xor_sync(~0u, s0, 2);
                s1 += __shfl_xor_sync(~0u, s1, 1);
                s1 += __shfl_xor_sync(~0u, s1, 2);
                if (l4 == 0) {
                    pmax[wn][rowl] = mx0;     psum[wn][rowl] = s0;
                    pmax[wn][rowl + 8] = mx1; psum[wn][rowl + 8] = s1;
                }
            }
            __syncthreads();
            if (tid < 128) {
                float m0 = pmax[0][tid], m1 = pmax[1][tid];
                float m2 = pmax[2][tid], m3 = pmax[3][tid];
                float mo = rmax[tid];
                float mn = fmaxf(fmaxf(fmaxf(m0, m1), fmaxf(m2, m3)), mo);
                rsum[tid] = rsum[tid] * __expf(mo - mn)
                          + psum[0][tid] * __expf(m0 - mn)
                          + psum[1][tid] * __expf(m1 - mn)
                          + psum[2][tid] * __expf(m2 - mn)
                          + psum[3][tid] * __expf(m3 - mn);
                rmax[tid] = mn;
            }
        }
    }

    __syncthreads();
    if (tid < 128) slse[tid] = rmax[tid] + logf(rsum[tid]);
    __syncthreads();
    float4* ob = (float4*)(out + ((size_t)r0 << 13));
    #pragma unroll 4
    for (int it = 0; it < 1024; ++it) {
        int idx = it * 256 + tid;
        float l = slse[idx >> 11];
        float4 x = ob[idx];
        x.x -= l; x.y -= l; x.z -= l; x.w -= l;
        ob[idx] = x;
    }
}

extern "C" void kernel_launch(void* const* d_in, const int* in_sizes, int n_in,
                              void* d_out, int out_size) {
    (void)in_sizes; (void)n_in; (void)out_size;
    const float* v  = (const float*)d_in[0];
    const float* t  = (const float*)d_in[1];
    const float* W1 = (const float*)d_in[2];
    const float* b1 = (const float*)d_in[3];
    const float* W2 = (const float*)d_in[4];
    const float* b2 = (const float*)d_in[5];
    const float* Wv = (const float*)d_in[6];
    const float* bvp = (const float*)d_in[7];
    float* out = (float*)d_out;

    k_encdec<<<640, 256>>>(v, t, W1, b1, W2, b2);
    k_cvt<<<4096, 256>>>(Wv);
    k_cvt2<<<1024, 256>>>();
    cudaFuncSetAttribute(k_gemm2, cudaFuncAttributeMaxDynamicSharedMemorySize, DYN_SMEM);
    k_gemm2<<<256, 256, DYN_SMEM>>>(bvp, out);
}

// round 10
// speedup vs baseline: 2.0147x; 2.0147x over previous
#include <cuda_runtime.h>
#include <cuda_fp16.h>
#include <math.h>
#include <stdint.h>

#define VSZ 8192

__device__ __align__(16) float g_enc[512 * 512];
__device__ __align__(16) float g_dec[128 * 512];
__device__ __align__(16) __half g_wvt[8192 * 512];   // [v][d] fp16

__device__ __forceinline__ uint32_t smem_u32(const void* p) {
    uint32_t a;
    asm("{ .reg .u64 t; cvta.to.shared.u64 t, %1; cvt.u32.u64 %0, t; }" : "=r"(a) : "l"(p));
    return a;
}
__device__ __forceinline__ void cpa16(uint32_t dst, const void* src) {
    asm volatile("cp.async.cg.shared.global [%0], [%1], 16;" :: "r"(dst), "l"(src));
}
#define CPA_COMMIT() asm volatile("cp.async.commit_group;" ::: "memory")
#define CPA_WAIT1()  asm volatile("cp.async.wait_group 1;" ::: "memory")
#define CPA_WAIT0()  asm volatile("cp.async.wait_group 0;" ::: "memory")
__device__ __forceinline__ void ldsm4(uint32_t* r, uint32_t a) {
    asm volatile("ldmatrix.sync.aligned.m8n8.x4.shared.b16 {%0,%1,%2,%3}, [%4];"
        : "=r"(r[0]), "=r"(r[1]), "=r"(r[2]), "=r"(r[3]) : "r"(a));
}
__device__ __forceinline__ void mma_h(uint32_t* c, const uint32_t* a, const uint32_t* b) {
    asm("mma.sync.aligned.m16n8k16.row.col.f16.f16.f16.f16 "
        "{%0,%1}, {%2,%3,%4,%5}, {%6,%7}, {%0,%1};\n"
        : "+r"(c[0]), "+r"(c[1])
        : "r"(a[0]), "r"(a[1]), "r"(a[2]), "r"(a[3]), "r"(b[0]), "r"(b[1]));
}

// ---------------- prep ----------------
__global__ void k_encdec(const float* __restrict__ v, const float* __restrict__ t,
                         const float* __restrict__ W1, const float* __restrict__ b1,
                         const float* __restrict__ W2, const float* __restrict__ b2) {
    __shared__ float xr[4][512];
    int bid = blockIdx.x, tid = threadIdx.x;
    int rg = bid >> 2, cq = bid & 3;
    const float *in, *W, *bs; float* out;
    if (rg < 128) { in = v + (size_t)rg * 2048; W = W1; bs = b1; out = g_enc + (size_t)rg * 2048; }
    else { in = t + (size_t)(rg - 128) * 2048; W = W2; bs = b2; out = g_dec + (size_t)(rg - 128) * 2048; }
    #pragma unroll
    for (int i = 0; i < 8; ++i) ((float*)xr)[i * 256 + tid] = in[i * 256 + tid];
    __syncthreads();
    int c = cq * 128 + (tid & 127);
    int rp = tid >> 7;
    float bb = bs[c];
    float a0 = bb, a1 = bb;
    #pragma unroll 4
    for (int d = 0; d < 512; ++d) {
        float w = W[d * 512 + c];
        a0 = fmaf(xr[rp][d], w, a0);
        a1 = fmaf(xr[rp + 2][d], w, a1);
    }
    out[(size_t)rp * 512 + c] = a0;
    out[(size_t)(rp + 2) * 512 + c] = a1;
}

__global__ void k_cvt(const float* __restrict__ Wv) {
    __shared__ float tile[32][33];
    int bvi = blockIdx.x & 255, bd = blockIdx.x >> 8;
    int v0 = bvi * 32, d0 = bd * 32;
    int c = threadIdx.x & 31, r8 = threadIdx.x >> 5;
    #pragma unroll
    for (int i = 0; i < 4; ++i)
        tile[i * 8 + r8][c] = Wv[(size_t)(d0 + i * 8 + r8) * VSZ + v0 + c];
    __syncthreads();
    #pragma unroll
    for (int i = 0; i < 4; ++i)
        g_wvt[(size_t)(v0 + i * 8 + r8) * 512 + d0 + c] = __float2half(tile[c][i * 8 + r8]);
}

// ---- main fp16 GEMM + fused log-softmax, occupancy 2 ----
// CTA: 64 rows x full V. 8 warps 2(M)x4(N), warp tile 32x32, f16 acc.
// N chunk 128 -> 64 chunks x 8 k-slabs (64k each) = 512 iters.
#define SA_STRB 1040
#define SB_STRB 144
#define A_BYTES (64 * SA_STRB)          // 66560
#define B_BYTES (128 * SB_STRB)         // 18432
#define DYN_SMEM (A_BYTES + 2 * B_BYTES) // 103424

__global__ void __launch_bounds__(256, 2)
k_gemm2(const float* __restrict__ bv, float* __restrict__ out) {
    extern __shared__ char sm[];
    __shared__ float pmax[4][64], psum[4][64];
    __shared__ float rmax[64], rsum[64], slse[64];

    const uint32_t sA = smem_u32(sm);
    const uint32_t sB0 = sA + A_BYTES;
    int tid = threadIdx.x, lane = tid & 31, w = tid >> 5;
    int wm = w >> 2, wn = w & 3;           // 2(M) x 4(N)
    int q = lane >> 2, l4 = lane & 3;
    int r0 = blockIdx.x * 64;

    // ---- build A tile (relu(enc+dec) -> fp16), 64 rows ----
    #pragma unroll 1
    for (int i = 0; i < 16; ++i) {
        int idx = i * 256 + tid;
        int r = idx >> 6, g = idx & 63;
        int grow = r0 + r;
        const float* ep = g_enc + (size_t)(grow >> 6) * 512 + g * 8;
        const float* dp = g_dec + (size_t)(((grow >> 14) << 6) | (grow & 63)) * 512 + g * 8;
        float4 e0 = *(const float4*)ep, e1 = *(const float4*)(ep + 4);
        float4 d0 = *(const float4*)dp, d1 = *(const float4*)(dp + 4);
        __half2 p0 = __floats2half2_rn(fmaxf(e0.x + d0.x, 0.f), fmaxf(e0.y + d0.y, 0.f));
        __half2 p1 = __floats2half2_rn(fmaxf(e0.z + d0.z, 0.f), fmaxf(e0.w + d0.w, 0.f));
        __half2 p2 = __floats2half2_rn(fmaxf(e1.x + d1.x, 0.f), fmaxf(e1.y + d1.y, 0.f));
        __half2 p3 = __floats2half2_rn(fmaxf(e1.z + d1.z, 0.f), fmaxf(e1.w + d1.w, 0.f));
        uint4 u;
        u.x = *(unsigned*)&p0; u.y = *(unsigned*)&p1; u.z = *(unsigned*)&p2; u.w = *(unsigned*)&p3;
        *(uint4*)(sm + r * SA_STRB + g * 16) = u;
    }
    if (tid < 64) { rmax[tid] = -1e30f; rsum[tid] = 0.f; }

    const uint32_t aBase = sA + (wm * 32 + (lane & 15)) * SA_STRB + (lane >> 4) * 16;
    const int bN = (lane & 7) + ((lane >> 4) << 3);
    const uint32_t bKh = ((lane >> 3) & 1) * 16;
    const uint32_t bBase = sB0 + (wn * 32 + bN) * SB_STRB + bKh;

    uint32_t acc[2][4][2];   // f16x2, 16 regs

    // stage slab 0: 128n x 128B, 4 x 16B per thread
    #pragma unroll
    for (int i = 0; i < 4; ++i) {
        int flat = i * 256 + tid;
        int n = flat >> 3, c = flat & 7;
        cpa16(sB0 + n * SB_STRB + c * 16, (const char*)g_wvt + (size_t)n * 1024 + c * 16);
    }
    CPA_COMMIT();

    #pragma unroll 1
    for (int s = 0; s < 512; ++s) {
        int vc = s >> 3, kb = s & 7, buf = s & 1;
        __syncthreads();
        if (s + 1 < 512) {
            int vn = (s + 1) >> 3, kn = (s + 1) & 7;
            uint32_t dst = sB0 + ((s + 1) & 1) * B_BYTES;
            const char* src = (const char*)g_wvt + (size_t)vn * 128 * 1024 + kn * 128;
            #pragma unroll
            for (int i = 0; i < 4; ++i) {
                int flat = i * 256 + tid;
                int n = flat >> 3, c = flat & 7;
                cpa16(dst + n * SB_STRB + c * 16, src + (size_t)n * 1024 + c * 16);
            }
            CPA_COMMIT();
            CPA_WAIT1();
        } else {
            CPA_WAIT0();
        }
        __syncthreads();

        if (kb == 0) {
            #pragma unroll
            for (int am = 0; am < 2; ++am)
                #pragma unroll
                for (int an = 0; an < 4; ++an) { acc[am][an][0] = 0u; acc[am][an][1] = 0u; }
        }

        uint32_t bB = bBase + buf * B_BYTES;
        uint32_t aK = aBase + kb * 128;
        #pragma unroll
        for (int ks = 0; ks < 4; ++ks) {
            uint32_t afr[2][4], bfr[2][4];
            #pragma unroll
            for (int am = 0; am < 2; ++am) ldsm4(afr[am], aK + am * 16 * SA_STRB + ks * 32);
            #pragma unroll
            for (int t = 0; t < 2; ++t) ldsm4(bfr[t], bB + t * 16 * SB_STRB + ks * 32);
            #pragma unroll
            for (int am = 0; am < 2; ++am)
                #pragma unroll
                for (int t = 0; t < 2; ++t) {
                    mma_h(acc[am][2 * t],     afr[am], &bfr[t][0]);
                    mma_h(acc[am][2 * t + 1], afr[am], &bfr[t][2]);
                }
        }

        if (kb == 7) {
            int v0 = vc * 128;
            #pragma unroll
            for (int am = 0; am < 2; ++am) {
                int rowl = wm * 32 + am * 16 + q;
                size_t gr0 = (size_t)(r0 + rowl) << 13;
                size_t gr1 = gr0 + (8u << 13);
                float mx0 = -1e30f, mx1 = -1e30f;
                float z[4][4];
                #pragma unroll
                for (int an = 0; an < 4; ++an) {
                    int cc = v0 + wn * 32 + an * 8 + l4 * 2;
                    float2 bv2 = __ldg((const float2*)&bv[cc]);
                    float2 f0 = __half22float2(*(__half2*)&acc[am][an][0]);
                    float2 f1 = __half22float2(*(__half2*)&acc[am][an][1]);
                    z[an][0] = f0.x + bv2.x; z[an][1] = f0.y + bv2.y;
                    z[an][2] = f1.x + bv2.x; z[an][3] = f1.y + bv2.y;
                    *(float2*)&out[gr0 + cc] = make_float2(z[an][0], z[an][1]);
                    *(float2*)&out[gr1 + cc] = make_float2(z[an][2], z[an][3]);
                    mx0 = fmaxf(mx0, fmaxf(z[an][0], z[an][1]));
                    mx1 = fmaxf(mx1, fmaxf(z[an][2], z[an][3]));
                }
                mx0 = fmaxf(mx0, __shfl_xor_sync(~0u, mx0, 1));
                mx0 = fmaxf(mx0, __shfl_xor_sync(~0u, mx0, 2));
                mx1 = fmaxf(mx1, __shfl_xor_sync(~0u, mx1, 1));
                mx1 = fmaxf(mx1, __shfl_xor_sync(~0u, mx1, 2));
                float s0 = 0.f, s1 = 0.f;
                #pragma unroll
                for (int an = 0; an < 4; ++an) {
                    s0 += __expf(z[an][0] - mx0) + __expf(z[an][1] - mx0);
                    s1 += __expf(z[an][2] - mx1) + __expf(z[an][3] - mx1);
                }
                s0 += __shfl_xor_sync(~0u, s0, 1);
                s0 += __shfl_xor_sync(~0u, s0, 2);
                s1 += __shfl_xor_sync(~0u, s1, 1);
                s1 += __shfl_xor_sync(~0u, s1, 2);
                if (l4 == 0) {
                    pmax[wn][rowl] = mx0;     psum[wn][rowl] = s0;
                    pmax[wn][rowl + 8] = mx1; psum[wn][rowl + 8] = s1;
                }
            }
            __syncthreads();
            if (tid < 64) {
                float m0 = pmax[0][tid], m1 = pmax[1][tid];
                float m2 = pmax[2][tid], m3 = pmax[3][tid];
                float mo = rmax[tid];
                float mn = fmaxf(fmaxf(fmaxf(m0, m1), fmaxf(m2, m3)), mo);
                rsum[tid] = rsum[tid] * __expf(mo - mn)
                          + psum[0][tid] * __expf(m0 - mn)
                          + psum[1][tid] * __expf(m1 - mn)
                          + psum[2][tid] * __expf(m2 - mn)
                          + psum[3][tid] * __expf(m3 - mn);
                rmax[tid] = mn;
            }
        }
    }

    // ---- fused fixup over this CTA's 64 rows ----
    __syncthreads();
    if (tid < 64) slse[tid] = rmax[tid] + logf(rsum[tid]);
    __syncthreads();
    float4* ob = (float4*)(out + ((size_t)r0 << 13));
    #pragma unroll 4
    for (int it = 0; it < 512; ++it) {
        int idx = it * 256 + tid;
        float l = slse[idx >> 11];
        float4 x = ob[idx];
        x.x -= l; x.y -= l; x.z -= l; x.w -= l;
        ob[idx] = x;
    }
}

extern "C" void kernel_launch(void* const* d_in, const int* in_sizes, int n_in,
                              void* d_out, int out_size) {
    (void)in_sizes; (void)n_in; (void)out_size;
    const float* v  = (const float*)d_in[0];
    const float* t  = (const float*)d_in[1];
    const float* W1 = (const float*)d_in[2];
    const float* b1 = (const float*)d_in[3];
    const float* W2 = (const float*)d_in[4];
    const float* b2 = (const float*)d_in[5];
    const float* Wv = (const float*)d_in[6];
    const float* bvp = (const float*)d_in[7];
    float* out = (float*)d_out;

    k_encdec<<<640, 256>>>(v, t, W1, b1, W2, b2);
    k_cvt<<<4096, 256>>>(Wv);
    cudaFuncSetAttribute(k_gemm2, cudaFuncAttributeMaxDynamicSharedMemorySize, DYN_SMEM);
    k_gemm2<<<512, 256, DYN_SMEM>>>(bvp, out);
}